// round 13
// baseline (speedup 1.0000x reference)
#include <cuda_runtime.h>
#include <cuda_bf16.h>
#include <mma.h>
#include <cstdint>

using namespace nvcuda;

#define Hdim 256
#define Sdim 512
#define Bdim 256
#define G3   768

// 402 MB scratch for precomputed input-gate activations gi[b*S + t][768]
__device__ float g_gi[(size_t)Bdim * Sdim * G3];

typedef unsigned long long u64;
__device__ __forceinline__ u64 pack2(float lo, float hi) {
    u64 r; asm("mov.b64 %0,{%1,%2};" : "=l"(r) : "f"(lo), "f"(hi)); return r;
}
__device__ __forceinline__ void unpack2(u64 v, float& lo, float& hi) {
    asm("mov.b64 {%0,%1},%2;" : "=f"(lo), "=f"(hi) : "l"(v));
}
__device__ __forceinline__ u64 ffma2(u64 a, u64 b, u64 c) {
    u64 d; asm("fma.rn.f32x2 %0,%1,%2,%3;" : "=l"(d) : "l"(a), "l"(b), "l"(c));
    return d;
}

// split float4 -> packed bf16x4 hi and lo (x = hi + lo)
__device__ __forceinline__ void cvt_split4(const float4 v, u64& hi_u, u64& lo_u) {
    __nv_bfloat16 h0 = __float2bfloat16(v.x), h1 = __float2bfloat16(v.y);
    __nv_bfloat16 h2 = __float2bfloat16(v.z), h3 = __float2bfloat16(v.w);
    float l0 = v.x - __bfloat162float(h0), l1 = v.y - __bfloat162float(h1);
    float l2 = v.z - __bfloat162float(h2), l3 = v.w - __bfloat162float(h3);
    union { __nv_bfloat162 b2[2]; u64 u; } uh, ul;
    uh.b2[0] = __nv_bfloat162(h0, h1); uh.b2[1] = __nv_bfloat162(h2, h3);
    ul.b2[0] = __nv_bfloat162(__float2bfloat16(l0), __float2bfloat16(l1));
    ul.b2[1] = __nv_bfloat162(__float2bfloat16(l2), __float2bfloat16(l3));
    hi_u = uh.u; lo_u = ul.u;
}

// ---------------------------------------------------------------------------
// Kernel 1: gi = x @ W_ih^T + b_ih, fused convert + bf16 WMMA (3-product split)
//   gi ~= Ah*Wh + Al*Wh + Ah*Wl   (fp32 accum)
// v13: CTA tile 128(M) x 64(N), 8 warps (4m x 2n), warp tile 32x32.
// Small tile -> ~100 regs, 31.7 KB smem -> 2-3 CTAs/SM co-resident, hiding
// the load/convert/sync phases that single-residency exposed.
// ---------------------------------------------------------------------------
#define AL  136                       // A tile ldm (m-stride padded)
#define LDB 40                        // B tile ldm
#define OF_AH 0
#define OF_AL 8704                    // 32*136*2
#define OF_BH 17408                   // + 32*136*2
#define OF_BL 22528                   // + 64*40*2
#define OF_BIAS 27648                 // + 64*40*2
#define GSM_TOTAL (OF_BIAS + 16 * 64 * 4)    // 31,744 B

__global__ __launch_bounds__(256) void gi_mma_kernel(const float* __restrict__ seq,
                                                     const float* __restrict__ W_ih,
                                                     const float* __restrict__ b_ih) {
    extern __shared__ __align__(16) char smg[];
    __nv_bfloat16* As_h = (__nv_bfloat16*)(smg + OF_AH);
    __nv_bfloat16* As_l = (__nv_bfloat16*)(smg + OF_AL);
    __nv_bfloat16* Bs_h = (__nv_bfloat16*)(smg + OF_BH);
    __nv_bfloat16* Bs_l = (__nv_bfloat16*)(smg + OF_BL);
    float*         bias = (float*)(smg + OF_BIAS);

    const int tid = threadIdx.x;
    const int wid = tid >> 5;
    const int wm  = wid >> 1;         // warp rows [wm*32, +32)
    const int wn  = wid & 1;          // warp cols [wn*32, +32)
    const int b   = blockIdx.x >> 2;
    const int t0  = (blockIdx.x & 3) * 128;
    const int n0  = blockIdx.y * 64;
    const size_t mbase = (size_t)b * Sdim + t0;
    const float* seqb = seq + (size_t)b * (Hdim * Sdim);

    // per-thread load coordinates: 4 A float4s + 2 B float4s per kb
    int akr[4], atc[4], brow[2], bg[2];
#pragma unroll
    for (int q = 0; q < 4; ++q) {
        int i = tid + q * 256;
        akr[q] = i >> 5;  atc[q] = i & 31;     // A: 32 k-rows x 32 float4 (t)
    }
#pragma unroll
    for (int q = 0; q < 2; ++q) {
        int i = tid + q * 256;
        brow[q] = i >> 3; bg[q] = i & 7;       // B: 64 n-rows x 8 float4 (k)
    }

    // bias broadcast tile: 16 identical rows of 64
    for (int i = tid; i < 16 * 64; i += 256) bias[i] = b_ih[n0 + (i & 63)];
    __syncthreads();

    wmma::fragment<wmma::accumulator, 16, 16, 16, float> c[2][2];
#pragma unroll
    for (int i = 0; i < 2; ++i)
#pragma unroll
        for (int j = 0; j < 2; ++j)
            wmma::load_matrix_sync(c[i][j], bias + wn * 32 + j * 16, 64,
                                   wmma::mem_row_major);

    float4 rA[4], rB[2];
#pragma unroll
    for (int q = 0; q < 4; ++q)            // prefetch kb = 0
        rA[q] = *(const float4*)(seqb + (size_t)akr[q] * Sdim + t0 + atc[q] * 4);
#pragma unroll
    for (int q = 0; q < 2; ++q)
        rB[q] = *(const float4*)(W_ih + (size_t)(n0 + brow[q]) * Hdim + bg[q] * 4);

    for (int kb = 0; kb < 8; ++kb) {
        // convert regs -> smem bf16 hi/lo tiles
#pragma unroll
        for (int q = 0; q < 4; ++q) {
            u64 h, l;
            cvt_split4(rA[q], h, l);
            int so = akr[q] * AL + atc[q] * 4;   // [k][m]
            *(u64*)(As_h + so) = h;
            *(u64*)(As_l + so) = l;
        }
#pragma unroll
        for (int q = 0; q < 2; ++q) {
            u64 h, l;
            cvt_split4(rB[q], h, l);
            int so = brow[q] * LDB + bg[q] * 4;  // [n][k]
            *(u64*)(Bs_h + so) = h;
            *(u64*)(Bs_l + so) = l;
        }
        __syncthreads();

        if (kb < 7) {                    // prefetch kb+1 under the mma block
            int ko = (kb + 1) * 32;
#pragma unroll
            for (int q = 0; q < 4; ++q)
                rA[q] = *(const float4*)(seqb + (size_t)(ko + akr[q]) * Sdim + t0 + atc[q] * 4);
#pragma unroll
            for (int q = 0; q < 2; ++q)
                rB[q] = *(const float4*)(W_ih + (size_t)(n0 + brow[q]) * Hdim + ko + bg[q] * 4);
        }

#pragma unroll
        for (int ks = 0; ks < 2; ++ks) {
            wmma::fragment<wmma::matrix_a, 16, 16, 16, __nv_bfloat16, wmma::col_major> ah[2], al[2];
            wmma::fragment<wmma::matrix_b, 16, 16, 16, __nv_bfloat16, wmma::col_major> bh[2], bl[2];
#pragma unroll
            for (int i = 0; i < 2; ++i) {
                wmma::load_matrix_sync(ah[i], As_h + ks * 16 * AL + wm * 32 + i * 16, AL);
                wmma::load_matrix_sync(al[i], As_l + ks * 16 * AL + wm * 32 + i * 16, AL);
            }
#pragma unroll
            for (int j = 0; j < 2; ++j) {
                wmma::load_matrix_sync(bh[j], Bs_h + (wn * 32 + j * 16) * LDB + ks * 16, LDB);
                wmma::load_matrix_sync(bl[j], Bs_l + (wn * 32 + j * 16) * LDB + ks * 16, LDB);
            }
#pragma unroll
            for (int i = 0; i < 2; ++i)
#pragma unroll
                for (int j = 0; j < 2; ++j) {
                    wmma::mma_sync(c[i][j], ah[i], bh[j], c[i][j]);
                    wmma::mma_sync(c[i][j], al[i], bh[j], c[i][j]);
                    wmma::mma_sync(c[i][j], ah[i], bl[j], c[i][j]);
                }
        }
        __syncthreads();
    }

    // store to g_gi (row-major, ldm = G3)
#pragma unroll
    for (int i = 0; i < 2; ++i)
#pragma unroll
        for (int j = 0; j < 2; ++j) {
            float* dst = g_gi + (mbase + wm * 32 + i * 16) * G3 + n0 + wn * 32 + j * 16;
            wmma::store_matrix_sync(dst, c[i][j], G3, wmma::mem_row_major);
        }
}

// ---------------------------------------------------------------------------
// Kernel 2: persistent GRU recurrence v7 (round-10 exact — 1.605 ms measured).
// ---------------------------------------------------------------------------
#define WS 264
#define HS 260
#define WS_FLOATS (192 * WS)
#define HB_FLOATS (2 * 8 * HS)
#define RSM_BYTES ((WS_FLOATS + HB_FLOATS + 8) * 4)

__device__ __forceinline__ float sigm(float x) {
    return __fdividef(1.f, 1.f + __expf(-x));
}
__device__ __forceinline__ float tanh_e(float x) {
    return __fdividef(2.f, 1.f + __expf(-2.f * x)) - 1.f;
}

__global__ __launch_bounds__(256, 1) __cluster_dims__(4, 1, 1)
void gru_rec_kernel(const float* __restrict__ tree,
                    const int*   __restrict__ mask,
                    const float* __restrict__ W_hh,
                    const float* __restrict__ b_hh,
                    float*       __restrict__ out) {
    extern __shared__ __align__(16) float sm[];
    float* W_s   = sm;
    float* h_buf = sm + WS_FLOATS;
    int*   li_s  = (int*)(h_buf + HB_FLOATS);

    const int tid = threadIdx.x;
    const int r   = blockIdx.x & 3;
    const int b0  = (blockIdx.x >> 2) * 8;

    for (int i = tid; i < 192 * 256; i += 256) {
        int row = i >> 8, k = i & 255;
        int grow = (row >> 6) * 256 + r * 64 + (row & 63);
        W_s[row * WS + k] = W_hh[(size_t)grow * 256 + k];
    }
    for (int i = tid; i < 8 * 256; i += 256)
        h_buf[(i >> 8) * HS + (i & 255)] = tree[(size_t)b0 * 256 + i];
    {
        int bb = tid >> 5, ln = tid & 31;
        int s = 0;
        for (int i = ln; i < 512; i += 32) s += mask[(size_t)(b0 + bb) * 512 + i];
#pragma unroll
        for (int o = 16; o; o >>= 1) s += __shfl_xor_sync(0xffffffffu, s, o);
        if (ln == 0) li_s[bb] = (s > 0) ? (s - 1) : 0;
    }
    __syncthreads();
    asm volatile("barrier.cluster.arrive.aligned;" ::: "memory");
    asm volatile("barrier.cluster.wait.aligned;" ::: "memory");

    const int lane = tid & 31;
    const int w    = tid >> 5;
    const int kc   = lane & 7;
    const int jg   = w * 4 + (lane >> 3);
    const int kglob = r * 64 + jg * 2;

    const float* wb[3][2];
#pragma unroll
    for (int g = 0; g < 3; ++g)
#pragma unroll
        for (int jl = 0; jl < 2; ++jl)
            wb[g][jl] = W_s + (g * 64 + jg * 2 + jl) * WS + kc * 4;

    const float2 bhr2 = *(const float2*)(b_hh + kglob);
    const float2 bhz2 = *(const float2*)(b_hh + 256 + kglob);
    const float2 bhn2 = *(const float2*)(b_hh + 512 + kglob);
    const int li = li_s[kc];

    uint32_t hb_u32;
    asm("{ .reg .u64 t0; cvta.to.shared.u64 t0, %1; cvt.u32.u64 %0, t0; }"
        : "=r"(hb_u32) : "l"(h_buf));
    uint32_t peer[4];
#pragma unroll
    for (int q = 0; q < 4; ++q)
        asm("mapa.shared::cluster.u32 %0, %1, %2;" : "=r"(peer[q]) : "r"(hb_u32), "r"(q));

    const float* gp = g_gi + ((size_t)(b0 + kc) * Sdim) * G3 + kglob;
    float2 gr2 = *(const float2*)(gp);
    float2 gz2 = *(const float2*)(gp + 256);
    float2 gn2 = *(const float2*)(gp + 512);

    const int k0 = kc & 1, k1 = (kc >> 1) & 1, k2 = (kc >> 2) & 1;

    int p = 0;
    for (int t = 0; t < Sdim; ++t) {
        const float* hbp = h_buf + p * (8 * HS) + kc * 4;
        u64 acc[3][2][8];
#pragma unroll
        for (int g = 0; g < 3; ++g)
#pragma unroll
            for (int jl = 0; jl < 2; ++jl)
#pragma unroll
                for (int b = 0; b < 8; ++b) acc[g][jl][b] = 0ull;

#pragma unroll
        for (int m = 0; m < 8; ++m) {
            ulonglong2 wv[3][2];
#pragma unroll
            for (int g = 0; g < 3; ++g)
#pragma unroll
                for (int jl = 0; jl < 2; ++jl)
                    wv[g][jl] = *(const ulonglong2*)(wb[g][jl] + 32 * m);
#pragma unroll
            for (int b = 0; b < 8; ++b) {
                ulonglong2 hv = *(const ulonglong2*)(hbp + b * HS + 32 * m);
#pragma unroll
                for (int g = 0; g < 3; ++g)
#pragma unroll
                    for (int jl = 0; jl < 2; ++jl) {
                        acc[g][jl][b] = ffma2(wv[g][jl].x, hv.x, acc[g][jl][b]);
                        acc[g][jl][b] = ffma2(wv[g][jl].y, hv.y, acc[g][jl][b]);
                    }
            }
        }

        float s0[3][2][8];
#pragma unroll
        for (int g = 0; g < 3; ++g)
#pragma unroll
            for (int jl = 0; jl < 2; ++jl)
#pragma unroll
                for (int b = 0; b < 8; ++b) {
                    float lo, hi; unpack2(acc[g][jl][b], lo, hi);
                    s0[g][jl][b] = lo + hi;
                }
        float s1[3][2][4];
#pragma unroll
        for (int g = 0; g < 3; ++g)
#pragma unroll
            for (int jl = 0; jl < 2; ++jl)
#pragma unroll
                for (int b = 0; b < 4; ++b) {
                    float e = s0[g][jl][2 * b], o = s0[g][jl][2 * b + 1];
                    float keep = k0 ? o : e, send = k0 ? e : o;
                    s1[g][jl][b] = keep + __shfl_xor_sync(0xffffffffu, send, 1);
                }
        float s2[3][2][2];
#pragma unroll
        for (int g = 0; g < 3; ++g)
#pragma unroll
            for (int jl = 0; jl < 2; ++jl)
#pragma unroll
                for (int b = 0; b < 2; ++b) {
                    float e = s1[g][jl][2 * b], o = s1[g][jl][2 * b + 1];
                    float keep = k1 ? o : e, send = k1 ? e : o;
                    s2[g][jl][b] = keep + __shfl_xor_sync(0xffffffffu, send, 2);
                }
        float sf[3][2];
#pragma unroll
        for (int g = 0; g < 3; ++g)
#pragma unroll
            for (int jl = 0; jl < 2; ++jl) {
                float e = s2[g][jl][0], o = s2[g][jl][1];
                float keep = k2 ? o : e, send = k2 ? e : o;
                sf[g][jl] = keep + __shfl_xor_sync(0xffffffffu, send, 4);
            }

        const float2 hold2 = *(const float2*)(h_buf + p * (8 * HS) + kc * HS + kglob);
        float r0 = sigm(gr2.x + bhr2.x + sf[0][0]);
        float z0 = sigm(gz2.x + bhz2.x + sf[1][0]);
        float n0 = tanh_e(fmaf(r0, sf[2][0] + bhn2.x, gn2.x));
        float hn0 = fmaf(z0, hold2.x - n0, n0);
        float r1 = sigm(gr2.y + bhr2.y + sf[0][1]);
        float z1 = sigm(gz2.y + bhz2.y + sf[1][1]);
        float n1 = tanh_e(fmaf(r1, sf[2][1] + bhn2.y, gn2.y));
        float hn1 = fmaf(z1, hold2.y - n1, n1);

        if (t == li)
            *(float2*)(out + (size_t)(b0 + kc) * 256 + kglob) = make_float2(hn0, hn1);

        int pn = p ^ 1;
        u64 hv2 = pack2(hn0, hn1);
        uint32_t off = (uint32_t)(((pn * 8 + kc) * HS + kglob) * 4);
#pragma unroll
        for (int q = 0; q < 4; ++q)
            asm volatile("st.shared::cluster.u64 [%0], %1;"
                         :: "r"(peer[q] + off), "l"(hv2) : "memory");

        asm volatile("barrier.cluster.arrive.aligned;" ::: "memory");
        gp += G3;
        if (t + 1 < Sdim) {
            gr2 = *(const float2*)(gp);
            gz2 = *(const float2*)(gp + 256);
            gn2 = *(const float2*)(gp + 512);
        }
        asm volatile("barrier.cluster.wait.aligned;" ::: "memory");
        p = pn;
    }
}

// ---------------------------------------------------------------------------
extern "C" void kernel_launch(void* const* d_in, const int* in_sizes, int n_in,
                              void* d_out, int out_size) {
    const float* tree  = (const float*)d_in[0];
    const float* seq   = (const float*)d_in[1];
    const int*   mask  = (const int*)  d_in[2];
    const float* W_ih  = (const float*)d_in[3];
    const float* W_hh  = (const float*)d_in[4];
    const float* b_ih  = (const float*)d_in[5];
    const float* b_hh  = (const float*)d_in[6];
    float* out = (float*)d_out;

    cudaFuncSetAttribute(gi_mma_kernel,
                         cudaFuncAttributeMaxDynamicSharedMemorySize, GSM_TOTAL);
    dim3 g1((Bdim * Sdim) / 128, G3 / 64);
    gi_mma_kernel<<<g1, 256, GSM_TOTAL>>>(seq, W_ih, b_ih);

    cudaFuncSetAttribute(gru_rec_kernel,
                         cudaFuncAttributeMaxDynamicSharedMemorySize, RSM_BYTES);
    gru_rec_kernel<<<128, 256, RSM_BYTES>>>(tree, mask, W_hh, b_hh, out);
}

// round 14
// speedup vs baseline: 1.1676x; 1.1676x over previous
#include <cuda_runtime.h>
#include <cuda_fp16.h>
#include <mma.h>
#include <cstdint>

using namespace nvcuda;

#define Hdim 256
#define Sdim 512
#define Bdim 256
#define G3   768

// 402 MB scratch for precomputed input-gate activations gi[b*S + t][768]
__device__ float g_gi[(size_t)Bdim * Sdim * G3];

typedef unsigned long long u64;
__device__ __forceinline__ u64 pack2(float lo, float hi) {
    u64 r; asm("mov.b64 %0,{%1,%2};" : "=l"(r) : "f"(lo), "f"(hi)); return r;
}
__device__ __forceinline__ void unpack2(u64 v, float& lo, float& hi) {
    asm("mov.b64 {%0,%1},%2;" : "=f"(lo), "=f"(hi) : "l"(v));
}
__device__ __forceinline__ u64 ffma2(u64 a, u64 b, u64 c) {
    u64 d; asm("fma.rn.f32x2 %0,%1,%2,%3;" : "=l"(d) : "l"(a), "l"(b), "l"(c));
    return d;
}

// convert float4 -> packed half4 (u64)
__device__ __forceinline__ u64 cvt_half4(const float4 v) {
    union { __half2 h2[2]; u64 u; } r;
    r.h2[0] = __float22half2_rn(make_float2(v.x, v.y));
    r.h2[1] = __float22half2_rn(make_float2(v.z, v.w));
    return r.u;
}

// ---------------------------------------------------------------------------
// Kernel 1: gi = x @ W_ih^T + b_ih, fused convert + SINGLE-PRODUCT fp16 WMMA.
// fp16 (11 mantissa bits): gi error ~eps_fp16 ~5e-4 -> final rel_err ~1.5e-4,
// inside the 1e-3 budget. 3x fewer MACs than the bf16 3-term split; the
// wmma path was HMMA-throughput-bound, so this cuts the GEMM ~2-3x.
// Round-10 structure otherwise: CTA 128x128, 8 warps (4m x 2n), warp 32x64,
// register prefetch of kb+1 under the mma block.
// ---------------------------------------------------------------------------
#define AL  136                       // A tile ldm (m-stride padded, halfs)
#define LDB 40                        // B tile ldm (halfs)
#define OF_A  0
#define OF_B  8704                    // 32*136*2
#define OF_BIAS 18944                 // + 128*40*2
#define GSM_TOTAL (OF_BIAS + 16 * 128 * 4)   // 27,136 B

__global__ __launch_bounds__(256) void gi_mma_kernel(const float* __restrict__ seq,
                                                     const float* __restrict__ W_ih,
                                                     const float* __restrict__ b_ih) {
    extern __shared__ __align__(16) char smg[];
    __half* As = (__half*)(smg + OF_A);
    __half* Bs = (__half*)(smg + OF_B);
    float*  bias = (float*)(smg + OF_BIAS);

    const int tid = threadIdx.x;
    const int wid = tid >> 5;
    const int wm  = wid >> 1;         // warp rows [wm*32, +32)
    const int wn  = wid & 1;          // warp cols [wn*64, +64)
    const int b   = blockIdx.x >> 2;
    const int t0  = (blockIdx.x & 3) * 128;
    const int n0  = blockIdx.y * 128;
    const size_t mbase = (size_t)b * Sdim + t0;
    const float* seqb = seq + (size_t)b * (Hdim * Sdim);

    // per-thread load coordinates (4 A + 4 B float4s per kb)
    int akr[4], atc[4], brow[4], bg[4];
#pragma unroll
    for (int q = 0; q < 4; ++q) {
        int i = tid + q * 256;
        akr[q] = i >> 5;  atc[q] = i & 31;     // A: 32 k-rows x 32 float4 (t)
        brow[q] = i >> 3; bg[q] = i & 7;       // B: 128 n-rows x 8 float4 (k)
    }

    // bias broadcast tile: 16 identical rows of 128
    for (int i = tid; i < 16 * 128; i += 256) bias[i] = b_ih[n0 + (i & 127)];
    __syncthreads();

    wmma::fragment<wmma::accumulator, 16, 16, 16, float> c[2][4];
#pragma unroll
    for (int i = 0; i < 2; ++i)
#pragma unroll
        for (int j = 0; j < 4; ++j)
            wmma::load_matrix_sync(c[i][j], bias + wn * 64 + j * 16, 128,
                                   wmma::mem_row_major);

    float4 rA[4], rB[4];
#pragma unroll
    for (int q = 0; q < 4; ++q) {          // prefetch kb = 0
        rA[q] = *(const float4*)(seqb + (size_t)akr[q] * Sdim + t0 + atc[q] * 4);
        rB[q] = *(const float4*)(W_ih + (size_t)(n0 + brow[q]) * Hdim + bg[q] * 4);
    }

    for (int kb = 0; kb < 8; ++kb) {
        // convert regs -> smem fp16 tiles
#pragma unroll
        for (int q = 0; q < 4; ++q) {
            *(u64*)(As + akr[q] * AL + atc[q] * 4) = cvt_half4(rA[q]);   // [k][m]
            *(u64*)(Bs + brow[q] * LDB + bg[q] * 4) = cvt_half4(rB[q]);  // [n][k]
        }
        __syncthreads();

        if (kb < 7) {                    // prefetch kb+1 under the mma block
            int ko = (kb + 1) * 32;
#pragma unroll
            for (int q = 0; q < 4; ++q) {
                rA[q] = *(const float4*)(seqb + (size_t)(ko + akr[q]) * Sdim + t0 + atc[q] * 4);
                rB[q] = *(const float4*)(W_ih + (size_t)(n0 + brow[q]) * Hdim + ko + bg[q] * 4);
            }
        }

#pragma unroll
        for (int ks = 0; ks < 2; ++ks) {
            wmma::fragment<wmma::matrix_a, 16, 16, 16, __half, wmma::col_major> a[2];
            wmma::fragment<wmma::matrix_b, 16, 16, 16, __half, wmma::col_major> bfr[4];
#pragma unroll
            for (int i = 0; i < 2; ++i)
                wmma::load_matrix_sync(a[i], As + ks * 16 * AL + wm * 32 + i * 16, AL);
#pragma unroll
            for (int j = 0; j < 4; ++j)
                wmma::load_matrix_sync(bfr[j], Bs + (wn * 64 + j * 16) * LDB + ks * 16, LDB);
#pragma unroll
            for (int i = 0; i < 2; ++i)
#pragma unroll
                for (int j = 0; j < 4; ++j)
                    wmma::mma_sync(c[i][j], a[i], bfr[j], c[i][j]);
        }
        __syncthreads();
    }

    // store to g_gi (row-major, ldm = G3)
#pragma unroll
    for (int i = 0; i < 2; ++i)
#pragma unroll
        for (int j = 0; j < 4; ++j) {
            float* dst = g_gi + (mbase + wm * 32 + i * 16) * G3 + n0 + wn * 64 + j * 16;
            wmma::store_matrix_sync(dst, c[i][j], G3, wmma::mem_row_major);
        }
}

// ---------------------------------------------------------------------------
// Kernel 2: persistent GRU recurrence v7 (round-10 exact — 1.605 ms measured).
// ---------------------------------------------------------------------------
#define WS 264
#define HS 260
#define WS_FLOATS (192 * WS)
#define HB_FLOATS (2 * 8 * HS)
#define RSM_BYTES ((WS_FLOATS + HB_FLOATS + 8) * 4)

__device__ __forceinline__ float sigm(float x) {
    return __fdividef(1.f, 1.f + __expf(-x));
}
__device__ __forceinline__ float tanh_e(float x) {
    return __fdividef(2.f, 1.f + __expf(-2.f * x)) - 1.f;
}

__global__ __launch_bounds__(256, 1) __cluster_dims__(4, 1, 1)
void gru_rec_kernel(const float* __restrict__ tree,
                    const int*   __restrict__ mask,
                    const float* __restrict__ W_hh,
                    const float* __restrict__ b_hh,
                    float*       __restrict__ out) {
    extern __shared__ __align__(16) float sm[];
    float* W_s   = sm;
    float* h_buf = sm + WS_FLOATS;
    int*   li_s  = (int*)(h_buf + HB_FLOATS);

    const int tid = threadIdx.x;
    const int r   = blockIdx.x & 3;
    const int b0  = (blockIdx.x >> 2) * 8;

    for (int i = tid; i < 192 * 256; i += 256) {
        int row = i >> 8, k = i & 255;
        int grow = (row >> 6) * 256 + r * 64 + (row & 63);
        W_s[row * WS + k] = W_hh[(size_t)grow * 256 + k];
    }
    for (int i = tid; i < 8 * 256; i += 256)
        h_buf[(i >> 8) * HS + (i & 255)] = tree[(size_t)b0 * 256 + i];
    {
        int bb = tid >> 5, ln = tid & 31;
        int s = 0;
        for (int i = ln; i < 512; i += 32) s += mask[(size_t)(b0 + bb) * 512 + i];
#pragma unroll
        for (int o = 16; o; o >>= 1) s += __shfl_xor_sync(0xffffffffu, s, o);
        if (ln == 0) li_s[bb] = (s > 0) ? (s - 1) : 0;
    }
    __syncthreads();
    asm volatile("barrier.cluster.arrive.aligned;" ::: "memory");
    asm volatile("barrier.cluster.wait.aligned;" ::: "memory");

    const int lane = tid & 31;
    const int w    = tid >> 5;
    const int kc   = lane & 7;
    const int jg   = w * 4 + (lane >> 3);
    const int kglob = r * 64 + jg * 2;

    const float* wb[3][2];
#pragma unroll
    for (int g = 0; g < 3; ++g)
#pragma unroll
        for (int jl = 0; jl < 2; ++jl)
            wb[g][jl] = W_s + (g * 64 + jg * 2 + jl) * WS + kc * 4;

    const float2 bhr2 = *(const float2*)(b_hh + kglob);
    const float2 bhz2 = *(const float2*)(b_hh + 256 + kglob);
    const float2 bhn2 = *(const float2*)(b_hh + 512 + kglob);
    const int li = li_s[kc];

    uint32_t hb_u32;
    asm("{ .reg .u64 t0; cvta.to.shared.u64 t0, %1; cvt.u32.u64 %0, t0; }"
        : "=r"(hb_u32) : "l"(h_buf));
    uint32_t peer[4];
#pragma unroll
    for (int q = 0; q < 4; ++q)
        asm("mapa.shared::cluster.u32 %0, %1, %2;" : "=r"(peer[q]) : "r"(hb_u32), "r"(q));

    const float* gp = g_gi + ((size_t)(b0 + kc) * Sdim) * G3 + kglob;
    float2 gr2 = *(const float2*)(gp);
    float2 gz2 = *(const float2*)(gp + 256);
    float2 gn2 = *(const float2*)(gp + 512);

    const int k0 = kc & 1, k1 = (kc >> 1) & 1, k2 = (kc >> 2) & 1;

    int p = 0;
    for (int t = 0; t < Sdim; ++t) {
        const float* hbp = h_buf + p * (8 * HS) + kc * 4;
        u64 acc[3][2][8];
#pragma unroll
        for (int g = 0; g < 3; ++g)
#pragma unroll
            for (int jl = 0; jl < 2; ++jl)
#pragma unroll
                for (int b = 0; b < 8; ++b) acc[g][jl][b] = 0ull;

#pragma unroll
        for (int m = 0; m < 8; ++m) {
            ulonglong2 wv[3][2];
#pragma unroll
            for (int g = 0; g < 3; ++g)
#pragma unroll
                for (int jl = 0; jl < 2; ++jl)
                    wv[g][jl] = *(const ulonglong2*)(wb[g][jl] + 32 * m);
#pragma unroll
            for (int b = 0; b < 8; ++b) {
                ulonglong2 hv = *(const ulonglong2*)(hbp + b * HS + 32 * m);
#pragma unroll
                for (int g = 0; g < 3; ++g)
#pragma unroll
                    for (int jl = 0; jl < 2; ++jl) {
                        acc[g][jl][b] = ffma2(wv[g][jl].x, hv.x, acc[g][jl][b]);
                        acc[g][jl][b] = ffma2(wv[g][jl].y, hv.y, acc[g][jl][b]);
                    }
            }
        }

        float s0[3][2][8];
#pragma unroll
        for (int g = 0; g < 3; ++g)
#pragma unroll
            for (int jl = 0; jl < 2; ++jl)
#pragma unroll
                for (int b = 0; b < 8; ++b) {
                    float lo, hi; unpack2(acc[g][jl][b], lo, hi);
                    s0[g][jl][b] = lo + hi;
                }
        float s1[3][2][4];
#pragma unroll
        for (int g = 0; g < 3; ++g)
#pragma unroll
            for (int jl = 0; jl < 2; ++jl)
#pragma unroll
                for (int b = 0; b < 4; ++b) {
                    float e = s0[g][jl][2 * b], o = s0[g][jl][2 * b + 1];
                    float keep = k0 ? o : e, send = k0 ? e : o;
                    s1[g][jl][b] = keep + __shfl_xor_sync(0xffffffffu, send, 1);
                }
        float s2[3][2][2];
#pragma unroll
        for (int g = 0; g < 3; ++g)
#pragma unroll
            for (int jl = 0; jl < 2; ++jl)
#pragma unroll
                for (int b = 0; b < 2; ++b) {
                    float e = s1[g][jl][2 * b], o = s1[g][jl][2 * b + 1];
                    float keep = k1 ? o : e, send = k1 ? e : o;
                    s2[g][jl][b] = keep + __shfl_xor_sync(0xffffffffu, send, 2);
                }
        float sf[3][2];
#pragma unroll
        for (int g = 0; g < 3; ++g)
#pragma unroll
            for (int jl = 0; jl < 2; ++jl) {
                float e = s2[g][jl][0], o = s2[g][jl][1];
                float keep = k2 ? o : e, send = k2 ? e : o;
                sf[g][jl] = keep + __shfl_xor_sync(0xffffffffu, send, 4);
            }

        const float2 hold2 = *(const float2*)(h_buf + p * (8 * HS) + kc * HS + kglob);
        float r0 = sigm(gr2.x + bhr2.x + sf[0][0]);
        float z0 = sigm(gz2.x + bhz2.x + sf[1][0]);
        float n0 = tanh_e(fmaf(r0, sf[2][0] + bhn2.x, gn2.x));
        float hn0 = fmaf(z0, hold2.x - n0, n0);
        float r1 = sigm(gr2.y + bhr2.y + sf[0][1]);
        float z1 = sigm(gz2.y + bhz2.y + sf[1][1]);
        float n1 = tanh_e(fmaf(r1, sf[2][1] + bhn2.y, gn2.y));
        float hn1 = fmaf(z1, hold2.y - n1, n1);

        if (t == li)
            *(float2*)(out + (size_t)(b0 + kc) * 256 + kglob) = make_float2(hn0, hn1);

        int pn = p ^ 1;
        u64 hv2 = pack2(hn0, hn1);
        uint32_t off = (uint32_t)(((pn * 8 + kc) * HS + kglob) * 4);
#pragma unroll
        for (int q = 0; q < 4; ++q)
            asm volatile("st.shared::cluster.u64 [%0], %1;"
                         :: "r"(peer[q] + off), "l"(hv2) : "memory");

        asm volatile("barrier.cluster.arrive.aligned;" ::: "memory");
        gp += G3;
        if (t + 1 < Sdim) {
            gr2 = *(const float2*)(gp);
            gz2 = *(const float2*)(gp + 256);
            gn2 = *(const float2*)(gp + 512);
        }
        asm volatile("barrier.cluster.wait.aligned;" ::: "memory");
        p = pn;
    }
}

// ---------------------------------------------------------------------------
extern "C" void kernel_launch(void* const* d_in, const int* in_sizes, int n_in,
                              void* d_out, int out_size) {
    const float* tree  = (const float*)d_in[0];
    const float* seq   = (const float*)d_in[1];
    const int*   mask  = (const int*)  d_in[2];
    const float* W_ih  = (const float*)d_in[3];
    const float* W_hh  = (const float*)d_in[4];
    const float* b_ih  = (const float*)d_in[5];
    const float* b_hh  = (const float*)d_in[6];
    float* out = (float*)d_out;

    cudaFuncSetAttribute(gi_mma_kernel,
                         cudaFuncAttributeMaxDynamicSharedMemorySize, GSM_TOTAL);
    dim3 g1((Bdim * Sdim) / 128, G3 / 128);
    gi_mma_kernel<<<g1, 256, GSM_TOTAL>>>(seq, W_ih, b_ih);

    cudaFuncSetAttribute(gru_rec_kernel,
                         cudaFuncAttributeMaxDynamicSharedMemorySize, RSM_BYTES);
    gru_rec_kernel<<<128, 256, RSM_BYTES>>>(tree, mask, W_hh, b_hh, out);
}

// round 15
// speedup vs baseline: 1.2263x; 1.0502x over previous
#include <cuda_runtime.h>
#include <cuda_fp16.h>
#include <mma.h>
#include <cstdint>

using namespace nvcuda;

#define Hdim 256
#define Sdim 512
#define Bdim 256
#define G3   768

// 402 MB scratch for precomputed input-gate activations gi[b*S + t][768]
__device__ float g_gi[(size_t)Bdim * Sdim * G3];

typedef unsigned long long u64;
__device__ __forceinline__ u64 pack2(float lo, float hi) {
    u64 r; asm("mov.b64 %0,{%1,%2};" : "=l"(r) : "f"(lo), "f"(hi)); return r;
}
__device__ __forceinline__ void unpack2(u64 v, float& lo, float& hi) {
    asm("mov.b64 {%0,%1},%2;" : "=f"(lo), "=f"(hi) : "l"(v));
}
__device__ __forceinline__ u64 ffma2(u64 a, u64 b, u64 c) {
    u64 d; asm("fma.rn.f32x2 %0,%1,%2,%3;" : "=l"(d) : "l"(a), "l"(b), "l"(c));
    return d;
}

// convert float4 -> packed half4 (u64)
__device__ __forceinline__ u64 cvt_half4(const float4 v) {
    union { __half2 h2[2]; u64 u; } r;
    r.h2[0] = __float22half2_rn(make_float2(v.x, v.y));
    r.h2[1] = __float22half2_rn(make_float2(v.z, v.w));
    return r.u;
}

// ---------------------------------------------------------------------------
// Kernel 1: gi = x @ W_ih^T + b_ih, fused convert + single-product fp16 WMMA.
// R14 structure (424 us) + __launch_bounds__(256,2): fp16 needs ~160 regs;
// cap at 128 (few spills) buys 2 CTAs/SM to hide load/convert/sync phases.
// ---------------------------------------------------------------------------
#define AL  136                       // A tile ldm (m-stride padded, halfs)
#define LDB 40                        // B tile ldm (halfs)
#define OF_A  0
#define OF_B  8704                    // 32*136*2
#define OF_BIAS 18944                 // + 128*40*2
#define GSM_TOTAL (OF_BIAS + 16 * 128 * 4)   // 27,136 B

__global__ __launch_bounds__(256, 2) void gi_mma_kernel(const float* __restrict__ seq,
                                                        const float* __restrict__ W_ih,
                                                        const float* __restrict__ b_ih) {
    extern __shared__ __align__(16) char smg[];
    __half* As = (__half*)(smg + OF_A);
    __half* Bs = (__half*)(smg + OF_B);
    float*  bias = (float*)(smg + OF_BIAS);

    const int tid = threadIdx.x;
    const int wid = tid >> 5;
    const int wm  = wid >> 1;         // warp rows [wm*32, +32)
    const int wn  = wid & 1;          // warp cols [wn*64, +64)
    const int b   = blockIdx.x >> 2;
    const int t0  = (blockIdx.x & 3) * 128;
    const int n0  = blockIdx.y * 128;
    const size_t mbase = (size_t)b * Sdim + t0;
    const float* seqb = seq + (size_t)b * (Hdim * Sdim);

    int akr[4], atc[4], brow[4], bg[4];
#pragma unroll
    for (int q = 0; q < 4; ++q) {
        int i = tid + q * 256;
        akr[q] = i >> 5;  atc[q] = i & 31;     // A: 32 k-rows x 32 float4 (t)
        brow[q] = i >> 3; bg[q] = i & 7;       // B: 128 n-rows x 8 float4 (k)
    }

    for (int i = tid; i < 16 * 128; i += 256) bias[i] = b_ih[n0 + (i & 127)];
    __syncthreads();

    wmma::fragment<wmma::accumulator, 16, 16, 16, float> c[2][4];
#pragma unroll
    for (int i = 0; i < 2; ++i)
#pragma unroll
        for (int j = 0; j < 4; ++j)
            wmma::load_matrix_sync(c[i][j], bias + wn * 64 + j * 16, 128,
                                   wmma::mem_row_major);

    float4 rA[4], rB[4];
#pragma unroll
    for (int q = 0; q < 4; ++q) {          // prefetch kb = 0
        rA[q] = *(const float4*)(seqb + (size_t)akr[q] * Sdim + t0 + atc[q] * 4);
        rB[q] = *(const float4*)(W_ih + (size_t)(n0 + brow[q]) * Hdim + bg[q] * 4);
    }

    for (int kb = 0; kb < 8; ++kb) {
#pragma unroll
        for (int q = 0; q < 4; ++q) {
            *(u64*)(As + akr[q] * AL + atc[q] * 4) = cvt_half4(rA[q]);   // [k][m]
            *(u64*)(Bs + brow[q] * LDB + bg[q] * 4) = cvt_half4(rB[q]);  // [n][k]
        }
        __syncthreads();

        if (kb < 7) {                    // prefetch kb+1 under the mma block
            int ko = (kb + 1) * 32;
#pragma unroll
            for (int q = 0; q < 4; ++q) {
                rA[q] = *(const float4*)(seqb + (size_t)(ko + akr[q]) * Sdim + t0 + atc[q] * 4);
                rB[q] = *(const float4*)(W_ih + (size_t)(n0 + brow[q]) * Hdim + ko + bg[q] * 4);
            }
        }

#pragma unroll
        for (int ks = 0; ks < 2; ++ks) {
            wmma::fragment<wmma::matrix_a, 16, 16, 16, __half, wmma::col_major> a[2];
            wmma::fragment<wmma::matrix_b, 16, 16, 16, __half, wmma::col_major> bfr[4];
#pragma unroll
            for (int i = 0; i < 2; ++i)
                wmma::load_matrix_sync(a[i], As + ks * 16 * AL + wm * 32 + i * 16, AL);
#pragma unroll
            for (int j = 0; j < 4; ++j)
                wmma::load_matrix_sync(bfr[j], Bs + (wn * 64 + j * 16) * LDB + ks * 16, LDB);
#pragma unroll
            for (int i = 0; i < 2; ++i)
#pragma unroll
                for (int j = 0; j < 4; ++j)
                    wmma::mma_sync(c[i][j], a[i], bfr[j], c[i][j]);
        }
        __syncthreads();
    }

#pragma unroll
    for (int i = 0; i < 2; ++i)
#pragma unroll
        for (int j = 0; j < 4; ++j) {
            float* dst = g_gi + (mbase + wm * 32 + i * 16) * G3 + n0 + wn * 64 + j * 16;
            wmma::store_matrix_sync(dst, c[i][j], G3, wmma::mem_row_major);
        }
}

// ---------------------------------------------------------------------------
// Kernel 2: persistent GRU recurrence v8 = v7 + st.async/mbarrier step sync.
// Per-step cluster barrier (UCGABAR ~490 cyc) replaced by: each thread
// st.async's its packed u64 h-update to all 4 peers with complete_tx on the
// peer's step-parity mbarrier (expect_tx = 1024 threads * 8 B = 8192 B);
// wait = try_wait.parity.acquire.cluster. Two alternating barriers give a
// 2-step reuse distance; re-arm (arrive.expect_tx) by tid0 directly after
// wait(t) precedes tid0's own t+1 stores in program order, which any peer
// needs before it can issue t+2 stores -> no cross-phase arrivals.
// ---------------------------------------------------------------------------
#define WS 264
#define HS 260
#define WS_FLOATS (192 * WS)
#define HB_FLOATS (2 * 8 * HS)
#define RSM_BYTES (((WS_FLOATS + HB_FLOATS + 8) * 4) + 16)

__device__ __forceinline__ float sigm(float x) {
    return __fdividef(1.f, 1.f + __expf(-x));
}
__device__ __forceinline__ float tanh_e(float x) {
    return __fdividef(2.f, 1.f + __expf(-2.f * x)) - 1.f;
}

__global__ __launch_bounds__(256, 1) __cluster_dims__(4, 1, 1)
void gru_rec_kernel(const float* __restrict__ tree,
                    const int*   __restrict__ mask,
                    const float* __restrict__ W_hh,
                    const float* __restrict__ b_hh,
                    float*       __restrict__ out) {
    extern __shared__ __align__(16) float sm[];
    float* W_s   = sm;
    float* h_buf = sm + WS_FLOATS;
    int*   li_s  = (int*)(h_buf + HB_FLOATS);

    const int tid = threadIdx.x;
    const int r   = blockIdx.x & 3;
    const int b0  = (blockIdx.x >> 2) * 8;

    uint32_t hb_u32;
    asm("{ .reg .u64 t0; cvta.to.shared.u64 t0, %1; cvt.u32.u64 %0, t0; }"
        : "=r"(hb_u32) : "l"(h_buf));
    const uint32_t mb_base = hb_u32 + (HB_FLOATS + 8) * 4;   // after li_s[8]

    for (int i = tid; i < 192 * 256; i += 256) {
        int row = i >> 8, k = i & 255;
        int grow = (row >> 6) * 256 + r * 64 + (row & 63);
        W_s[row * WS + k] = W_hh[(size_t)grow * 256 + k];
    }
    for (int i = tid; i < 8 * 256; i += 256)
        h_buf[(i >> 8) * HS + (i & 255)] = tree[(size_t)b0 * 256 + i];
    {
        int bb = tid >> 5, ln = tid & 31;
        int s = 0;
        for (int i = ln; i < 512; i += 32) s += mask[(size_t)(b0 + bb) * 512 + i];
#pragma unroll
        for (int o = 16; o; o >>= 1) s += __shfl_xor_sync(0xffffffffu, s, o);
        if (ln == 0) li_s[bb] = (s > 0) ? (s - 1) : 0;
    }
    // init + arm both step-parity mbarriers (arrive count 1 = the arm itself)
    if (tid == 0) {
        asm volatile("mbarrier.init.shared.b64 [%0], 1;" :: "r"(mb_base) : "memory");
        asm volatile("mbarrier.init.shared.b64 [%0], 1;" :: "r"(mb_base + 8) : "memory");
        asm volatile("mbarrier.arrive.expect_tx.shared.b64 _, [%0], %1;"
                     :: "r"(mb_base), "r"(8192u) : "memory");
        asm volatile("mbarrier.arrive.expect_tx.shared.b64 _, [%0], %1;"
                     :: "r"(mb_base + 8), "r"(8192u) : "memory");
    }
    __syncthreads();
    asm volatile("barrier.cluster.arrive.aligned;" ::: "memory");
    asm volatile("barrier.cluster.wait.aligned;" ::: "memory");

    const int lane = tid & 31;
    const int w    = tid >> 5;
    const int kc   = lane & 7;
    const int jg   = w * 4 + (lane >> 3);
    const int kglob = r * 64 + jg * 2;

    const float* wb[3][2];
#pragma unroll
    for (int g = 0; g < 3; ++g)
#pragma unroll
        for (int jl = 0; jl < 2; ++jl)
            wb[g][jl] = W_s + (g * 64 + jg * 2 + jl) * WS + kc * 4;

    const float2 bhr2 = *(const float2*)(b_hh + kglob);
    const float2 bhz2 = *(const float2*)(b_hh + 256 + kglob);
    const float2 bhn2 = *(const float2*)(b_hh + 512 + kglob);
    const int li = li_s[kc];

    uint32_t peer[4], peer_mb[4];
#pragma unroll
    for (int q = 0; q < 4; ++q) {
        asm("mapa.shared::cluster.u32 %0, %1, %2;" : "=r"(peer[q])    : "r"(hb_u32),  "r"(q));
        asm("mapa.shared::cluster.u32 %0, %1, %2;" : "=r"(peer_mb[q]) : "r"(mb_base), "r"(q));
    }

    const float* gp = g_gi + ((size_t)(b0 + kc) * Sdim) * G3 + kglob;
    float2 gr2 = *(const float2*)(gp);
    float2 gz2 = *(const float2*)(gp + 256);
    float2 gn2 = *(const float2*)(gp + 512);

    const int k0 = kc & 1, k1 = (kc >> 1) & 1, k2 = (kc >> 2) & 1;

    int p = 0;
    for (int t = 0; t < Sdim; ++t) {
        const float* hbp = h_buf + p * (8 * HS) + kc * 4;
        u64 acc[3][2][8];
#pragma unroll
        for (int g = 0; g < 3; ++g)
#pragma unroll
            for (int jl = 0; jl < 2; ++jl)
#pragma unroll
                for (int b = 0; b < 8; ++b) acc[g][jl][b] = 0ull;

#pragma unroll
        for (int m = 0; m < 8; ++m) {
            ulonglong2 wv[3][2];
#pragma unroll
            for (int g = 0; g < 3; ++g)
#pragma unroll
                for (int jl = 0; jl < 2; ++jl)
                    wv[g][jl] = *(const ulonglong2*)(wb[g][jl] + 32 * m);
#pragma unroll
            for (int b = 0; b < 8; ++b) {
                ulonglong2 hv = *(const ulonglong2*)(hbp + b * HS + 32 * m);
#pragma unroll
                for (int g = 0; g < 3; ++g)
#pragma unroll
                    for (int jl = 0; jl < 2; ++jl) {
                        acc[g][jl][b] = ffma2(wv[g][jl].x, hv.x, acc[g][jl][b]);
                        acc[g][jl][b] = ffma2(wv[g][jl].y, hv.y, acc[g][jl][b]);
                    }
            }
        }

        float s0[3][2][8];
#pragma unroll
        for (int g = 0; g < 3; ++g)
#pragma unroll
            for (int jl = 0; jl < 2; ++jl)
#pragma unroll
                for (int b = 0; b < 8; ++b) {
                    float lo, hi; unpack2(acc[g][jl][b], lo, hi);
                    s0[g][jl][b] = lo + hi;
                }
        float s1[3][2][4];
#pragma unroll
        for (int g = 0; g < 3; ++g)
#pragma unroll
            for (int jl = 0; jl < 2; ++jl)
#pragma unroll
                for (int b = 0; b < 4; ++b) {
                    float e = s0[g][jl][2 * b], o = s0[g][jl][2 * b + 1];
                    float keep = k0 ? o : e, send = k0 ? e : o;
                    s1[g][jl][b] = keep + __shfl_xor_sync(0xffffffffu, send, 1);
                }
        float s2[3][2][2];
#pragma unroll
        for (int g = 0; g < 3; ++g)
#pragma unroll
            for (int jl = 0; jl < 2; ++jl)
#pragma unroll
                for (int b = 0; b < 2; ++b) {
                    float e = s1[g][jl][2 * b], o = s1[g][jl][2 * b + 1];
                    float keep = k1 ? o : e, send = k1 ? e : o;
                    s2[g][jl][b] = keep + __shfl_xor_sync(0xffffffffu, send, 2);
                }
        float sf[3][2];
#pragma unroll
        for (int g = 0; g < 3; ++g)
#pragma unroll
            for (int jl = 0; jl < 2; ++jl) {
                float e = s2[g][jl][0], o = s2[g][jl][1];
                float keep = k2 ? o : e, send = k2 ? e : o;
                sf[g][jl] = keep + __shfl_xor_sync(0xffffffffu, send, 4);
            }

        const float2 hold2 = *(const float2*)(h_buf + p * (8 * HS) + kc * HS + kglob);
        float r0 = sigm(gr2.x + bhr2.x + sf[0][0]);
        float z0 = sigm(gz2.x + bhz2.x + sf[1][0]);
        float n0 = tanh_e(fmaf(r0, sf[2][0] + bhn2.x, gn2.x));
        float hn0 = fmaf(z0, hold2.x - n0, n0);
        float r1 = sigm(gr2.y + bhr2.y + sf[0][1]);
        float z1 = sigm(gz2.y + bhz2.y + sf[1][1]);
        float n1 = tanh_e(fmaf(r1, sf[2][1] + bhn2.y, gn2.y));
        float hn1 = fmaf(z1, hold2.y - n1, n1);

        if (t == li)
            *(float2*)(out + (size_t)(b0 + kc) * 256 + kglob) = make_float2(hn0, hn1);

        int pn = p ^ 1;
        u64 hv2 = pack2(hn0, hn1);
        uint32_t doff  = (uint32_t)(((pn * 8 + kc) * HS + kglob) * 4);
        uint32_t mboff = (uint32_t)((t & 1) * 8);
#pragma unroll
        for (int q = 0; q < 4; ++q)
            asm volatile("st.async.shared::cluster.mbarrier::complete_tx::bytes.b64 "
                         "[%0], %1, [%2];"
                         :: "r"(peer[q] + doff), "l"(hv2), "r"(peer_mb[q] + mboff)
                         : "memory");

        gp += G3;
        if (t + 1 < Sdim) {           // gi(t+1) prefetch hidden under the wait
            gr2 = *(const float2*)(gp);
            gz2 = *(const float2*)(gp + 256);
            gn2 = *(const float2*)(gp + 512);
        }

        {   // wait for all 8192 bytes of step t
            uint32_t mlocal = mb_base + mboff;
            uint32_t par = (uint32_t)((t >> 1) & 1);
            uint32_t done = 0;
            while (!done)
                asm volatile("{ .reg .pred pp; "
                             "mbarrier.try_wait.parity.acquire.cluster.shared::cta.b64 "
                             "pp, [%1], %2; selp.b32 %0,1,0,pp; }"
                             : "=r"(done) : "r"(mlocal), "r"(par) : "memory");
        }
        // re-arm this barrier for step t+2 (precedes tid0's t+1 stores)
        if (tid == 0 && t + 2 < Sdim)
            asm volatile("mbarrier.arrive.expect_tx.shared.b64 _, [%0], %1;"
                         :: "r"(mb_base + mboff), "r"(8192u) : "memory");
        p = pn;
    }
}

// ---------------------------------------------------------------------------
extern "C" void kernel_launch(void* const* d_in, const int* in_sizes, int n_in,
                              void* d_out, int out_size) {
    const float* tree  = (const float*)d_in[0];
    const float* seq   = (const float*)d_in[1];
    const int*   mask  = (const int*)  d_in[2];
    const float* W_ih  = (const float*)d_in[3];
    const float* W_hh  = (const float*)d_in[4];
    const float* b_ih  = (const float*)d_in[5];
    const float* b_hh  = (const float*)d_in[6];
    float* out = (float*)d_out;

    cudaFuncSetAttribute(gi_mma_kernel,
                         cudaFuncAttributeMaxDynamicSharedMemorySize, GSM_TOTAL);
    dim3 g1((Bdim * Sdim) / 128, G3 / 128);
    gi_mma_kernel<<<g1, 256, GSM_TOTAL>>>(seq, W_ih, b_ih);

    cudaFuncSetAttribute(gru_rec_kernel,
                         cudaFuncAttributeMaxDynamicSharedMemorySize, RSM_BYTES);
    gru_rec_kernel<<<128, 256, RSM_BYTES>>>(tree, mask, W_hh, b_hh, out);
}

// round 16
// speedup vs baseline: 1.2398x; 1.0111x over previous
#include <cuda_runtime.h>
#include <cuda_fp16.h>
#include <mma.h>
#include <cstdint>

using namespace nvcuda;

#define Hdim 256
#define Sdim 512
#define Bdim 256
#define G3   768

// 402 MB scratch for precomputed input-gate activations gi[b*S + t][768]
__device__ float g_gi[(size_t)Bdim * Sdim * G3];

typedef unsigned long long u64;
__device__ __forceinline__ u64 pack2(float lo, float hi) {
    u64 r; asm("mov.b64 %0,{%1,%2};" : "=l"(r) : "f"(lo), "f"(hi)); return r;
}
__device__ __forceinline__ void unpack2(u64 v, float& lo, float& hi) {
    asm("mov.b64 {%0,%1},%2;" : "=f"(lo), "=f"(hi) : "l"(v));
}
__device__ __forceinline__ u64 ffma2(u64 a, u64 b, u64 c) {
    u64 d; asm("fma.rn.f32x2 %0,%1,%2,%3;" : "=l"(d) : "l"(a), "l"(b), "l"(c));
    return d;
}

// convert float4 -> packed half4 (u64)
__device__ __forceinline__ u64 cvt_half4(const float4 v) {
    union { __half2 h2[2]; u64 u; } r;
    r.h2[0] = __float22half2_rn(make_float2(v.x, v.y));
    r.h2[1] = __float22half2_rn(make_float2(v.z, v.w));
    return r.u;
}

// ---------------------------------------------------------------------------
// Kernel 1: gi = x @ W_ih^T + b_ih, fused convert + single-product fp16 WMMA,
// __launch_bounds__(256,2) for 2-CTA/SM co-residency (measured ~300 us).
// ---------------------------------------------------------------------------
#define AL  136                       // A tile ldm (m-stride padded, halfs)
#define LDB 40                        // B tile ldm (halfs)
#define OF_A  0
#define OF_B  8704                    // 32*136*2
#define OF_BIAS 18944                 // + 128*40*2
#define GSM_TOTAL (OF_BIAS + 16 * 128 * 4)   // 27,136 B

__global__ __launch_bounds__(256, 2) void gi_mma_kernel(const float* __restrict__ seq,
                                                        const float* __restrict__ W_ih,
                                                        const float* __restrict__ b_ih) {
    extern __shared__ __align__(16) char smg[];
    __half* As = (__half*)(smg + OF_A);
    __half* Bs = (__half*)(smg + OF_B);
    float*  bias = (float*)(smg + OF_BIAS);

    const int tid = threadIdx.x;
    const int wid = tid >> 5;
    const int wm  = wid >> 1;         // warp rows [wm*32, +32)
    const int wn  = wid & 1;          // warp cols [wn*64, +64)
    const int b   = blockIdx.x >> 2;
    const int t0  = (blockIdx.x & 3) * 128;
    const int n0  = blockIdx.y * 128;
    const size_t mbase = (size_t)b * Sdim + t0;
    const float* seqb = seq + (size_t)b * (Hdim * Sdim);

    int akr[4], atc[4], brow[4], bg[4];
#pragma unroll
    for (int q = 0; q < 4; ++q) {
        int i = tid + q * 256;
        akr[q] = i >> 5;  atc[q] = i & 31;     // A: 32 k-rows x 32 float4 (t)
        brow[q] = i >> 3; bg[q] = i & 7;       // B: 128 n-rows x 8 float4 (k)
    }

    for (int i = tid; i < 16 * 128; i += 256) bias[i] = b_ih[n0 + (i & 127)];
    __syncthreads();

    wmma::fragment<wmma::accumulator, 16, 16, 16, float> c[2][4];
#pragma unroll
    for (int i = 0; i < 2; ++i)
#pragma unroll
        for (int j = 0; j < 4; ++j)
            wmma::load_matrix_sync(c[i][j], bias + wn * 64 + j * 16, 128,
                                   wmma::mem_row_major);

    float4 rA[4], rB[4];
#pragma unroll
    for (int q = 0; q < 4; ++q) {          // prefetch kb = 0
        rA[q] = *(const float4*)(seqb + (size_t)akr[q] * Sdim + t0 + atc[q] * 4);
        rB[q] = *(const float4*)(W_ih + (size_t)(n0 + brow[q]) * Hdim + bg[q] * 4);
    }

    for (int kb = 0; kb < 8; ++kb) {
#pragma unroll
        for (int q = 0; q < 4; ++q) {
            *(u64*)(As + akr[q] * AL + atc[q] * 4) = cvt_half4(rA[q]);   // [k][m]
            *(u64*)(Bs + brow[q] * LDB + bg[q] * 4) = cvt_half4(rB[q]);  // [n][k]
        }
        __syncthreads();

        if (kb < 7) {                    // prefetch kb+1 under the mma block
            int ko = (kb + 1) * 32;
#pragma unroll
            for (int q = 0; q < 4; ++q) {
                rA[q] = *(const float4*)(seqb + (size_t)(ko + akr[q]) * Sdim + t0 + atc[q] * 4);
                rB[q] = *(const float4*)(W_ih + (size_t)(n0 + brow[q]) * Hdim + ko + bg[q] * 4);
            }
        }

#pragma unroll
        for (int ks = 0; ks < 2; ++ks) {
            wmma::fragment<wmma::matrix_a, 16, 16, 16, __half, wmma::col_major> a[2];
            wmma::fragment<wmma::matrix_b, 16, 16, 16, __half, wmma::col_major> bfr[4];
#pragma unroll
            for (int i = 0; i < 2; ++i)
                wmma::load_matrix_sync(a[i], As + ks * 16 * AL + wm * 32 + i * 16, AL);
#pragma unroll
            for (int j = 0; j < 4; ++j)
                wmma::load_matrix_sync(bfr[j], Bs + (wn * 64 + j * 16) * LDB + ks * 16, LDB);
#pragma unroll
            for (int i = 0; i < 2; ++i)
#pragma unroll
                for (int j = 0; j < 4; ++j)
                    wmma::mma_sync(c[i][j], a[i], bfr[j], c[i][j]);
        }
        __syncthreads();
    }

#pragma unroll
    for (int i = 0; i < 2; ++i)
#pragma unroll
        for (int j = 0; j < 4; ++j) {
            float* dst = g_gi + (mbase + wm * 32 + i * 16) * G3 + n0 + wn * 64 + j * 16;
            wmma::store_matrix_sync(dst, c[i][j], G3, wmma::mem_row_major);
        }
}

// ---------------------------------------------------------------------------
// Kernel 2: persistent GRU recurrence v7 (round-10 exact — 1605-1617 us
// measured across five rounds; st.async variant reverted, it was slower).
// ---------------------------------------------------------------------------
#define WS 264
#define HS 260
#define WS_FLOATS (192 * WS)
#define HB_FLOATS (2 * 8 * HS)
#define RSM_BYTES ((WS_FLOATS + HB_FLOATS + 8) * 4)

__device__ __forceinline__ float sigm(float x) {
    return __fdividef(1.f, 1.f + __expf(-x));
}
__device__ __forceinline__ float tanh_e(float x) {
    return __fdividef(2.f, 1.f + __expf(-2.f * x)) - 1.f;
}

__global__ __launch_bounds__(256, 1) __cluster_dims__(4, 1, 1)
void gru_rec_kernel(const float* __restrict__ tree,
                    const int*   __restrict__ mask,
                    const float* __restrict__ W_hh,
                    const float* __restrict__ b_hh,
                    float*       __restrict__ out) {
    extern __shared__ __align__(16) float sm[];
    float* W_s   = sm;
    float* h_buf = sm + WS_FLOATS;
    int*   li_s  = (int*)(h_buf + HB_FLOATS);

    const int tid = threadIdx.x;
    const int r   = blockIdx.x & 3;
    const int b0  = (blockIdx.x >> 2) * 8;

    for (int i = tid; i < 192 * 256; i += 256) {
        int row = i >> 8, k = i & 255;
        int grow = (row >> 6) * 256 + r * 64 + (row & 63);
        W_s[row * WS + k] = W_hh[(size_t)grow * 256 + k];
    }
    for (int i = tid; i < 8 * 256; i += 256)
        h_buf[(i >> 8) * HS + (i & 255)] = tree[(size_t)b0 * 256 + i];
    {
        int bb = tid >> 5, ln = tid & 31;
        int s = 0;
        for (int i = ln; i < 512; i += 32) s += mask[(size_t)(b0 + bb) * 512 + i];
#pragma unroll
        for (int o = 16; o; o >>= 1) s += __shfl_xor_sync(0xffffffffu, s, o);
        if (ln == 0) li_s[bb] = (s > 0) ? (s - 1) : 0;
    }
    __syncthreads();
    asm volatile("barrier.cluster.arrive.aligned;" ::: "memory");
    asm volatile("barrier.cluster.wait.aligned;" ::: "memory");

    const int lane = tid & 31;
    const int w    = tid >> 5;
    const int kc   = lane & 7;
    const int jg   = w * 4 + (lane >> 3);
    const int kglob = r * 64 + jg * 2;

    const float* wb[3][2];
#pragma unroll
    for (int g = 0; g < 3; ++g)
#pragma unroll
        for (int jl = 0; jl < 2; ++jl)
            wb[g][jl] = W_s + (g * 64 + jg * 2 + jl) * WS + kc * 4;

    const float2 bhr2 = *(const float2*)(b_hh + kglob);
    const float2 bhz2 = *(const float2*)(b_hh + 256 + kglob);
    const float2 bhn2 = *(const float2*)(b_hh + 512 + kglob);
    const int li = li_s[kc];

    uint32_t hb_u32;
    asm("{ .reg .u64 t0; cvta.to.shared.u64 t0, %1; cvt.u32.u64 %0, t0; }"
        : "=r"(hb_u32) : "l"(h_buf));
    uint32_t peer[4];
#pragma unroll
    for (int q = 0; q < 4; ++q)
        asm("mapa.shared::cluster.u32 %0, %1, %2;" : "=r"(peer[q]) : "r"(hb_u32), "r"(q));

    const float* gp = g_gi + ((size_t)(b0 + kc) * Sdim) * G3 + kglob;
    float2 gr2 = *(const float2*)(gp);
    float2 gz2 = *(const float2*)(gp + 256);
    float2 gn2 = *(const float2*)(gp + 512);

    const int k0 = kc & 1, k1 = (kc >> 1) & 1, k2 = (kc >> 2) & 1;

    int p = 0;
    for (int t = 0; t < Sdim; ++t) {
        const float* hbp = h_buf + p * (8 * HS) + kc * 4;
        u64 acc[3][2][8];
#pragma unroll
        for (int g = 0; g < 3; ++g)
#pragma unroll
            for (int jl = 0; jl < 2; ++jl)
#pragma unroll
                for (int b = 0; b < 8; ++b) acc[g][jl][b] = 0ull;

#pragma unroll
        for (int m = 0; m < 8; ++m) {
            ulonglong2 wv[3][2];
#pragma unroll
            for (int g = 0; g < 3; ++g)
#pragma unroll
                for (int jl = 0; jl < 2; ++jl)
                    wv[g][jl] = *(const ulonglong2*)(wb[g][jl] + 32 * m);
#pragma unroll
            for (int b = 0; b < 8; ++b) {
                ulonglong2 hv = *(const ulonglong2*)(hbp + b * HS + 32 * m);
#pragma unroll
                for (int g = 0; g < 3; ++g)
#pragma unroll
                    for (int jl = 0; jl < 2; ++jl) {
                        acc[g][jl][b] = ffma2(wv[g][jl].x, hv.x, acc[g][jl][b]);
                        acc[g][jl][b] = ffma2(wv[g][jl].y, hv.y, acc[g][jl][b]);
                    }
            }
        }

        float s0[3][2][8];
#pragma unroll
        for (int g = 0; g < 3; ++g)
#pragma unroll
            for (int jl = 0; jl < 2; ++jl)
#pragma unroll
                for (int b = 0; b < 8; ++b) {
                    float lo, hi; unpack2(acc[g][jl][b], lo, hi);
                    s0[g][jl][b] = lo + hi;
                }
        float s1[3][2][4];
#pragma unroll
        for (int g = 0; g < 3; ++g)
#pragma unroll
            for (int jl = 0; jl < 2; ++jl)
#pragma unroll
                for (int b = 0; b < 4; ++b) {
                    float e = s0[g][jl][2 * b], o = s0[g][jl][2 * b + 1];
                    float keep = k0 ? o : e, send = k0 ? e : o;
                    s1[g][jl][b] = keep + __shfl_xor_sync(0xffffffffu, send, 1);
                }
        float s2[3][2][2];
#pragma unroll
        for (int g = 0; g < 3; ++g)
#pragma unroll
            for (int jl = 0; jl < 2; ++jl)
#pragma unroll
                for (int b = 0; b < 2; ++b) {
                    float e = s1[g][jl][2 * b], o = s1[g][jl][2 * b + 1];
                    float keep = k1 ? o : e, send = k1 ? e : o;
                    s2[g][jl][b] = keep + __shfl_xor_sync(0xffffffffu, send, 2);
                }
        float sf[3][2];
#pragma unroll
        for (int g = 0; g < 3; ++g)
#pragma unroll
            for (int jl = 0; jl < 2; ++jl) {
                float e = s2[g][jl][0], o = s2[g][jl][1];
                float keep = k2 ? o : e, send = k2 ? e : o;
                sf[g][jl] = keep + __shfl_xor_sync(0xffffffffu, send, 4);
            }

        const float2 hold2 = *(const float2*)(h_buf + p * (8 * HS) + kc * HS + kglob);
        float r0 = sigm(gr2.x + bhr2.x + sf[0][0]);
        float z0 = sigm(gz2.x + bhz2.x + sf[1][0]);
        float n0 = tanh_e(fmaf(r0, sf[2][0] + bhn2.x, gn2.x));
        float hn0 = fmaf(z0, hold2.x - n0, n0);
        float r1 = sigm(gr2.y + bhr2.y + sf[0][1]);
        float z1 = sigm(gz2.y + bhz2.y + sf[1][1]);
        float n1 = tanh_e(fmaf(r1, sf[2][1] + bhn2.y, gn2.y));
        float hn1 = fmaf(z1, hold2.y - n1, n1);

        if (t == li)
            *(float2*)(out + (size_t)(b0 + kc) * 256 + kglob) = make_float2(hn0, hn1);

        int pn = p ^ 1;
        u64 hv2 = pack2(hn0, hn1);
        uint32_t off = (uint32_t)(((pn * 8 + kc) * HS + kglob) * 4);
#pragma unroll
        for (int q = 0; q < 4; ++q)
            asm volatile("st.shared::cluster.u64 [%0], %1;"
                         :: "r"(peer[q] + off), "l"(hv2) : "memory");

        asm volatile("barrier.cluster.arrive.aligned;" ::: "memory");
        gp += G3;
        if (t + 1 < Sdim) {
            gr2 = *(const float2*)(gp);
            gz2 = *(const float2*)(gp + 256);
            gn2 = *(const float2*)(gp + 512);
        }
        asm volatile("barrier.cluster.wait.aligned;" ::: "memory");
        p = pn;
    }
}

// ---------------------------------------------------------------------------
extern "C" void kernel_launch(void* const* d_in, const int* in_sizes, int n_in,
                              void* d_out, int out_size) {
    const float* tree  = (const float*)d_in[0];
    const float* seq   = (const float*)d_in[1];
    const int*   mask  = (const int*)  d_in[2];
    const float* W_ih  = (const float*)d_in[3];
    const float* W_hh  = (const float*)d_in[4];
    const float* b_ih  = (const float*)d_in[5];
    const float* b_hh  = (const float*)d_in[6];
    float* out = (float*)d_out;

    cudaFuncSetAttribute(gi_mma_kernel,
                         cudaFuncAttributeMaxDynamicSharedMemorySize, GSM_TOTAL);
    dim3 g1((Bdim * Sdim) / 128, G3 / 128);
    gi_mma_kernel<<<g1, 256, GSM_TOTAL>>>(seq, W_ih, b_ih);

    cudaFuncSetAttribute(gru_rec_kernel,
                         cudaFuncAttributeMaxDynamicSharedMemorySize, RSM_BYTES);
    gru_rec_kernel<<<128, 256, RSM_BYTES>>>(tree, mask, W_hh, b_hh, out);
}

// round 17
// speedup vs baseline: 1.5726x; 1.2684x over previous
#include <cuda_runtime.h>
#include <cuda_fp16.h>
#include <mma.h>
#include <cstdint>

using namespace nvcuda;

#define Hdim 256
#define Sdim 512
#define Bdim 256
#define G3   768

// 402 MB scratch for precomputed input-gate activations gi[b*S + t][768]
__device__ float g_gi[(size_t)Bdim * Sdim * G3];

typedef unsigned long long u64;

// convert float4 -> packed half4 (u64)
__device__ __forceinline__ u64 cvt_half4(const float4 v) {
    union { __half2 h2[2]; u64 u; } r;
    r.h2[0] = __float22half2_rn(make_float2(v.x, v.y));
    r.h2[1] = __float22half2_rn(make_float2(v.z, v.w));
    return r.u;
}

// ---------------------------------------------------------------------------
// Kernel 1: gi = x @ W_ih^T + b_ih, fused convert + single-product fp16 WMMA,
// __launch_bounds__(256,2) for 2-CTA/SM co-residency (R16 exact, ~313 us).
// ---------------------------------------------------------------------------
#define AL  136
#define LDB 40
#define OF_A  0
#define OF_B  8704
#define OF_BIAS 18944
#define GSM_TOTAL (OF_BIAS + 16 * 128 * 4)   // 27,136 B

__global__ __launch_bounds__(256, 2) void gi_mma_kernel(const float* __restrict__ seq,
                                                        const float* __restrict__ W_ih,
                                                        const float* __restrict__ b_ih) {
    extern __shared__ __align__(16) char smg[];
    __half* As = (__half*)(smg + OF_A);
    __half* Bs = (__half*)(smg + OF_B);
    float*  bias = (float*)(smg + OF_BIAS);

    const int tid = threadIdx.x;
    const int wid = tid >> 5;
    const int wm  = wid >> 1;
    const int wn  = wid & 1;
    const int b   = blockIdx.x >> 2;
    const int t0  = (blockIdx.x & 3) * 128;
    const int n0  = blockIdx.y * 128;
    const size_t mbase = (size_t)b * Sdim + t0;
    const float* seqb = seq + (size_t)b * (Hdim * Sdim);

    int akr[4], atc[4], brow[4], bg[4];
#pragma unroll
    for (int q = 0; q < 4; ++q) {
        int i = tid + q * 256;
        akr[q] = i >> 5;  atc[q] = i & 31;
        brow[q] = i >> 3; bg[q] = i & 7;
    }

    for (int i = tid; i < 16 * 128; i += 256) bias[i] = b_ih[n0 + (i & 127)];
    __syncthreads();

    wmma::fragment<wmma::accumulator, 16, 16, 16, float> c[2][4];
#pragma unroll
    for (int i = 0; i < 2; ++i)
#pragma unroll
        for (int j = 0; j < 4; ++j)
            wmma::load_matrix_sync(c[i][j], bias + wn * 64 + j * 16, 128,
                                   wmma::mem_row_major);

    float4 rA[4], rB[4];
#pragma unroll
    for (int q = 0; q < 4; ++q) {
        rA[q] = *(const float4*)(seqb + (size_t)akr[q] * Sdim + t0 + atc[q] * 4);
        rB[q] = *(const float4*)(W_ih + (size_t)(n0 + brow[q]) * Hdim + bg[q] * 4);
    }

    for (int kb = 0; kb < 8; ++kb) {
#pragma unroll
        for (int q = 0; q < 4; ++q) {
            *(u64*)(As + akr[q] * AL + atc[q] * 4) = cvt_half4(rA[q]);
            *(u64*)(Bs + brow[q] * LDB + bg[q] * 4) = cvt_half4(rB[q]);
        }
        __syncthreads();

        if (kb < 7) {
            int ko = (kb + 1) * 32;
#pragma unroll
            for (int q = 0; q < 4; ++q) {
                rA[q] = *(const float4*)(seqb + (size_t)(ko + akr[q]) * Sdim + t0 + atc[q] * 4);
                rB[q] = *(const float4*)(W_ih + (size_t)(n0 + brow[q]) * Hdim + ko + bg[q] * 4);
            }
        }

#pragma unroll
        for (int ks = 0; ks < 2; ++ks) {
            wmma::fragment<wmma::matrix_a, 16, 16, 16, __half, wmma::col_major> a[2];
            wmma::fragment<wmma::matrix_b, 16, 16, 16, __half, wmma::col_major> bfr[4];
#pragma unroll
            for (int i = 0; i < 2; ++i)
                wmma::load_matrix_sync(a[i], As + ks * 16 * AL + wm * 32 + i * 16, AL);
#pragma unroll
            for (int j = 0; j < 4; ++j)
                wmma::load_matrix_sync(bfr[j], Bs + (wn * 64 + j * 16) * LDB + ks * 16, LDB);
#pragma unroll
            for (int i = 0; i < 2; ++i)
#pragma unroll
                for (int j = 0; j < 4; ++j)
                    wmma::mma_sync(c[i][j], a[i], bfr[j], c[i][j]);
        }
        __syncthreads();
    }

#pragma unroll
    for (int i = 0; i < 2; ++i)
#pragma unroll
        for (int j = 0; j < 4; ++j) {
            float* dst = g_gi + (mbase + wm * 32 + i * 16) * G3 + n0 + wn * 64 + j * 16;
            wmma::store_matrix_sync(dst, c[i][j], G3, wmma::mem_row_major);
        }
}

// ---------------------------------------------------------------------------
// Kernel 2: persistent GRU recurrence v9 — HMMA dot product.
// Per step per CTA: gh(16x192) = h(16x256, rows 8-15 zero) @ W_slice^T via
// fp16 wmma, fp32 accum. 12 n-tiles split 2,2,2,2,1,1,1,1 over 8 warps
// (SMSP-balanced: warp w and w+4 share an SMSP -> 3 tiles each).
// C staged to smem (16x200 f32); epilogue thread (kc=b, jg dim-pair) reads
// its 3 gates, does GRU math with f32 reg-carried hold, broadcasts fp16 h
// to all 4 cluster CTAs; per-step cluster barrier orders everything.
// ---------------------------------------------------------------------------
#define W_LD 264                          // halfs per W_s row
#define H_LD 272                          // halfs per h_buf row
#define STG_LD 200                        // floats per stage row
#define OF_W   0
#define OF_H   (192 * W_LD * 2)           // 101,376
#define OF_STG (OF_H + 2 * 16 * H_LD * 2) // +17,408 = 118,784
#define OF_LI  (OF_STG + 16 * STG_LD * 4) // +12,800 = 131,584
#define RSM_BYTES (OF_LI + 64)

__device__ __forceinline__ float sigm(float x) {
    return __fdividef(1.f, 1.f + __expf(-x));
}
__device__ __forceinline__ float tanh_e(float x) {
    return __fdividef(2.f, 1.f + __expf(-2.f * x)) - 1.f;
}

__global__ __launch_bounds__(256, 1) __cluster_dims__(4, 1, 1)
void gru_rec_kernel(const float* __restrict__ tree,
                    const int*   __restrict__ mask,
                    const float* __restrict__ W_hh,
                    const float* __restrict__ b_hh,
                    float*       __restrict__ out) {
    extern __shared__ __align__(16) char smr[];
    __half* W_s   = (__half*)(smr + OF_W);    // [192][W_LD]: row = g*64+jt, col = k
    __half* h_buf = (__half*)(smr + OF_H);    // [2][16][H_LD]
    float*  stage = (float*)(smr + OF_STG);   // [16][STG_LD]
    int*    li_s  = (int*)(smr + OF_LI);

    const int tid = threadIdx.x;
    const int r   = blockIdx.x & 3;
    const int b0  = (blockIdx.x >> 2) * 8;

    // W_hh slice -> fp16 smem
    for (int i = tid; i < 192 * 256; i += 256) {
        int row = i >> 8, k = i & 255;
        int grow = (row >> 6) * 256 + r * 64 + (row & 63);
        W_s[row * W_LD + k] = __float2half(W_hh[(size_t)grow * 256 + k]);
    }
    // zero both h buffers (incl. pad rows 8-15), then fill rows 0-7 of buf 0
    for (int i = tid; i < 2 * 16 * H_LD; i += 256) h_buf[i] = __float2half(0.f);
    __syncthreads();
    for (int i = tid; i < 8 * 256; i += 256)
        h_buf[(i >> 8) * H_LD + (i & 255)] = __float2half(tree[(size_t)b0 * 256 + i]);
    {
        int bb = tid >> 5, ln = tid & 31;
        int s = 0;
        for (int i = ln; i < 512; i += 32) s += mask[(size_t)(b0 + bb) * 512 + i];
#pragma unroll
        for (int o = 16; o; o >>= 1) s += __shfl_xor_sync(0xffffffffu, s, o);
        if (ln == 0) li_s[bb] = (s > 0) ? (s - 1) : 0;
    }
    __syncthreads();
    asm volatile("barrier.cluster.arrive.aligned;" ::: "memory");
    asm volatile("barrier.cluster.wait.aligned;" ::: "memory");

    const int lane = tid & 31;
    const int w    = tid >> 5;
    const int kc   = lane & 7;            // owned batch row
    const int jg   = w * 4 + (lane >> 3); // owned dim pair {2jg, 2jg+1}
    const int kglob = r * 64 + jg * 2;

    // warp n-tile assignment: 2,2,2,2,1,1,1,1 (SMSP-balanced)
    const int nt0 = (w < 4) ? 2 * w : 8 + (w - 4);
    const int ntn = (w < 4) ? 2 : 1;

    const float2 bhr2 = *(const float2*)(b_hh + kglob);
    const float2 bhz2 = *(const float2*)(b_hh + 256 + kglob);
    const float2 bhn2 = *(const float2*)(b_hh + 512 + kglob);
    const int li = li_s[kc];

    uint32_t hb_u32;
    asm("{ .reg .u64 t0; cvta.to.shared.u64 t0, %1; cvt.u32.u64 %0, t0; }"
        : "=r"(hb_u32) : "l"(h_buf));
    uint32_t peer[4];
#pragma unroll
    for (int q = 0; q < 4; ++q)
        asm("mapa.shared::cluster.u32 %0, %1, %2;" : "=r"(peer[q]) : "r"(hb_u32), "r"(q));

    const float* gp = g_gi + ((size_t)(b0 + kc) * Sdim) * G3 + kglob;
    float2 gr2 = *(const float2*)(gp);
    float2 gz2 = *(const float2*)(gp + 256);
    float2 gn2 = *(const float2*)(gp + 512);

    // hold carried in f32 registers (owner: batch kc, dims kglob, kglob+1)
    float2 hold2 = *(const float2*)(tree + (size_t)(b0 + kc) * 256 + kglob);

    int p = 0;
    for (int t = 0; t < Sdim; ++t) {
        // ---- HMMA: gh = h @ W_slice^T --------------------------------------
        const __half* hb = h_buf + p * 16 * H_LD;
        wmma::fragment<wmma::accumulator, 16, 16, 16, float> c[2];
#pragma unroll
        for (int j = 0; j < 2; ++j)
            if (j < ntn) wmma::fill_fragment(c[j], 0.0f);
#pragma unroll 4
        for (int kt = 0; kt < 16; ++kt) {
            wmma::fragment<wmma::matrix_a, 16, 16, 16, __half, wmma::row_major> a;
            wmma::load_matrix_sync(a, hb + kt * 16, H_LD);
#pragma unroll
            for (int j = 0; j < 2; ++j)
                if (j < ntn) {
                    wmma::fragment<wmma::matrix_b, 16, 16, 16, __half, wmma::col_major> bf;
                    wmma::load_matrix_sync(bf, W_s + (nt0 + j) * 16 * W_LD + kt * 16, W_LD);
                    wmma::mma_sync(c[j], a, bf, c[j]);
                }
        }
#pragma unroll
        for (int j = 0; j < 2; ++j)
            if (j < ntn)
                wmma::store_matrix_sync(stage + (nt0 + j) * 16, c[j], STG_LD,
                                        wmma::mem_row_major);
        __syncthreads();

        // ---- epilogue: batch row kc, dims kglob, kglob+1 -------------------
        const float* st = stage + kc * STG_LD + 2 * jg;
        float2 sr = *(const float2*)(st);
        float2 sz = *(const float2*)(st + 64);
        float2 sn = *(const float2*)(st + 128);

        float r0 = sigm(gr2.x + bhr2.x + sr.x);
        float z0 = sigm(gz2.x + bhz2.x + sz.x);
        float n0 = tanh_e(fmaf(r0, sn.x + bhn2.x, gn2.x));
        float hn0 = fmaf(z0, hold2.x - n0, n0);
        float r1 = sigm(gr2.y + bhr2.y + sr.y);
        float z1 = sigm(gz2.y + bhz2.y + sz.y);
        float n1 = tanh_e(fmaf(r1, sn.y + bhn2.y, gn2.y));
        float hn1 = fmaf(z1, hold2.y - n1, n1);
        hold2 = make_float2(hn0, hn1);

        if (t == li)
            *(float2*)(out + (size_t)(b0 + kc) * 256 + kglob) = make_float2(hn0, hn1);

        // ---- broadcast fp16 h to all 4 cluster CTAs ------------------------
        int pn = p ^ 1;
        __half2 hh = __floats2half2_rn(hn0, hn1);
        uint32_t hv = *(uint32_t*)&hh;
        uint32_t off = (uint32_t)(((pn * 16 + kc) * H_LD + kglob) * 2);
#pragma unroll
        for (int q = 0; q < 4; ++q)
            asm volatile("st.shared::cluster.u32 [%0], %1;"
                         :: "r"(peer[q] + off), "r"(hv) : "memory");

        asm volatile("barrier.cluster.arrive.aligned;" ::: "memory");
        gp += G3;
        if (t + 1 < Sdim) {           // gi(t+1) prefetch hidden under barrier wait
            gr2 = *(const float2*)(gp);
            gz2 = *(const float2*)(gp + 256);
            gn2 = *(const float2*)(gp + 512);
        }
        asm volatile("barrier.cluster.wait.aligned;" ::: "memory");
        p = pn;
    }
}

// ---------------------------------------------------------------------------
extern "C" void kernel_launch(void* const* d_in, const int* in_sizes, int n_in,
                              void* d_out, int out_size) {
    const float* tree  = (const float*)d_in[0];
    const float* seq   = (const float*)d_in[1];
    const int*   mask  = (const int*)  d_in[2];
    const float* W_ih  = (const float*)d_in[3];
    const float* W_hh  = (const float*)d_in[4];
    const float* b_ih  = (const float*)d_in[5];
    const float* b_hh  = (const float*)d_in[6];
    float* out = (float*)d_out;

    cudaFuncSetAttribute(gi_mma_kernel,
                         cudaFuncAttributeMaxDynamicSharedMemorySize, GSM_TOTAL);
    dim3 g1((Bdim * Sdim) / 128, G3 / 128);
    gi_mma_kernel<<<g1, 256, GSM_TOTAL>>>(seq, W_ih, b_ih);

    cudaFuncSetAttribute(gru_rec_kernel,
                         cudaFuncAttributeMaxDynamicSharedMemorySize, RSM_BYTES);
    gru_rec_kernel<<<128, 256, RSM_BYTES>>>(tree, mask, W_hh, b_hh, out);
}